// round 16
// baseline (speedup 1.0000x reference)
#include <cuda_runtime.h>
#include <cuda_fp16.h>
#include <math.h>

// Problem constants
#define TT 1024
#define BB 64
#define DD 512
#define HH 512
#define KK 1024            // D + H
#define GG 2048            // 4*H
#define EPSV 1e-5f
#define MM (TT * BB)       // 65536
#define OUT_HC_OFF (TT * BB * HH)
#define NBLK 128           // persistent blocks (<= 148 SMs)
#define WRT 64             // writer blocks (phase 2)
#define THR 512
#define WST 264            // smem halfword stride (conflict-free)

// Scratch (device globals — no runtime allocation allowed)
__device__ __half g_xhi[(size_t)MM * DD];                // x hi, fp16
__device__ __half g_xlo[(size_t)MM * DD];                // x lo, fp16
__device__ __half g_w16[(size_t)GG * KK];                // W^T [n][k], fp16
__device__ __half g_h16[BB * HH];                        // recurrent h, fp16
__device__ float g_c0[BB * HH];
__device__ float g_part[2 * BB * GG];                     // 2 K-halves of gates
__device__ unsigned g_flags[NBLK * 8];                    // barrier flags, 32B apart

__device__ __forceinline__ void split2h(float v, __half& hi, __half& lo) {
    hi = __float2half(v);
    lo = __float2half(v - __half2float(hi));
}

// fp16 HMMA m16n8k16 -> f32
__device__ __forceinline__ void mma_f16(float* d, const unsigned* a, const unsigned* b) {
    asm volatile(
        "mma.sync.aligned.m16n8k16.row.col.f32.f16.f16.f32 "
        "{%0,%1,%2,%3}, {%4,%5,%6,%7}, {%8,%9}, {%0,%1,%2,%3};\n"
        : "+f"(d[0]), "+f"(d[1]), "+f"(d[2]), "+f"(d[3])
        : "r"(a[0]), "r"(a[1]), "r"(a[2]), "r"(a[3]), "r"(b[0]), "r"(b[1]));
}

__device__ __forceinline__ void ldsm_x4(unsigned* r, const void* p) {
    unsigned addr = (unsigned)__cvta_generic_to_shared(p);
    asm volatile("ldmatrix.sync.aligned.m8n8.x4.shared.b16 {%0,%1,%2,%3}, [%4];"
        : "=r"(r[0]), "=r"(r[1]), "=r"(r[2]), "=r"(r[3]) : "r"(addr));
}
__device__ __forceinline__ void ldsm_x2(unsigned* r, const void* p) {
    unsigned addr = (unsigned)__cvta_generic_to_shared(p);
    asm volatile("ldmatrix.sync.aligned.m8n8.x2.shared.b16 {%0,%1}, [%2];"
        : "=r"(r[0]), "=r"(r[1]) : "r"(addr));
}

__device__ __forceinline__ void cp16(void* smem_dst, const void* gsrc) {
    unsigned d = (unsigned)__cvta_generic_to_shared(smem_dst);
    asm volatile("cp.async.cg.shared.global [%0], [%1], 16;" :: "r"(d), "l"(gsrc));
}
__device__ __forceinline__ void cp_commit() {
    asm volatile("cp.async.commit_group;");
}

__device__ __forceinline__ void st_release(unsigned* p, unsigned v) {
    asm volatile("st.release.gpu.u32 [%0], %1;" :: "l"(p), "r"(v) : "memory");
}
__device__ __forceinline__ unsigned ld_acquire(unsigned* p) {
    unsigned v;
    asm volatile("ld.acquire.gpu.u32 %0, [%1];" : "=r"(v) : "l"(p) : "memory");
    return v;
}

// flag barrier pieces (R7-verified protocol)
__device__ __forceinline__ void bar_arrive(int blk, unsigned val) {
    __syncthreads();
    if (threadIdx.x == 0) st_release(&g_flags[blk * 8], val);
}
__device__ __forceinline__ void bar_wait_all(unsigned val) {
    if (threadIdx.x < NBLK) {
        while (ld_acquire(&g_flags[threadIdx.x * 8]) < val) { }
    }
    __syncthreads();
}
__device__ __forceinline__ void bar_wait_writers(unsigned val) {
    if (threadIdx.x < WRT) {
        while (ld_acquire(&g_flags[threadIdx.x * 8]) < val) { }
    }
    __syncthreads();
}

__device__ __forceinline__ float fast_sig(float x) {
    return __fdividef(1.f, 1.f + __expf(-x));
}
__device__ __forceinline__ float fast_tanh(float x) {
    return __fdividef(2.f, 1.f + __expf(-2.f * x)) - 1.f;
}

// ---------------------------------------------------------------------------
__global__ void init_kernel(const float* __restrict__ h0,
                            const float* __restrict__ c0) {
    int i = blockIdx.x * blockDim.x + threadIdx.x;
    if (i < NBLK * 8) g_flags[i] = 0;
    if (i < BB * HH) {
        g_h16[i] = __float2half(h0[i]);
        g_c0[i] = c0[i];
    }
}

__global__ void split_w_kernel(const float* __restrict__ w) {
    int idx = blockIdx.x * blockDim.x + threadIdx.x;
    if (idx < KK * GG) {
        int k = idx / GG;
        int n = idx % GG;
        g_w16[(size_t)n * KK + k] = __float2half(w[idx]);
    }
}

__global__ void split_x_kernel(const float* __restrict__ x) {
    size_t idx = (size_t)blockIdx.x * blockDim.x + threadIdx.x;
    if (idx < (size_t)MM * DD) {
        __half hi, lo;
        split2h(x[idx], hi, lo);
        g_xhi[idx] = hi;
        g_xlo[idx] = lo;
    }
}

// ---------------------------------------------------------------------------
// fast two-level block reduction (512 threads = 16 warps) — verified
// ---------------------------------------------------------------------------
__device__ __forceinline__ void block_reduce2(float& s, float& sq, float* shm) {
    int lane = threadIdx.x & 31;
    int wrp = threadIdx.x >> 5;
#pragma unroll
    for (int o = 16; o > 0; o >>= 1) {
        s  += __shfl_xor_sync(0xffffffffu, s, o);
        sq += __shfl_xor_sync(0xffffffffu, sq, o);
    }
    if (lane == 0) { shm[wrp] = s; shm[16 + wrp] = sq; }
    __syncthreads();
    if (wrp == 0) {
        float a = (lane < 16) ? shm[lane] : 0.f;
        float b = (lane < 16) ? shm[16 + lane] : 0.f;
#pragma unroll
        for (int o = 8; o > 0; o >>= 1) {
            a += __shfl_xor_sync(0xffffffffu, a, o);
            b += __shfl_xor_sync(0xffffffffu, b, o);
        }
        if (lane == 0) { shm[0] = a; shm[16] = b; }
    }
    __syncthreads();
    s = shm[0];
    sq = shm[16];
}

// ---------------------------------------------------------------------------
// Fully fused persistent LSTM: 128 blocks x 512 threads (16 warps = 4m x 4n).
// Block = (jn = blk & 63 -> N cols [32jn,32jn+32), kc = blk >> 6 -> K half).
// Per step t:  gates_partial = x_t(hi+lo) @ Wx  +  h @ Wh   (+ bias on kc==0)
//   - x-partial (accx) for step t computed in the PREVIOUS iteration's
//     barrier-wait window from a cp.async double-buffered x tile.
//   - h-MMA accumulates on top of accx (critical path: 1 MMA term, K=256).
// Phase 2 (blocks 0..63): LN + activations for batch row b = blk.
// ---------------------------------------------------------------------------
__global__ void __launch_bounds__(THR, 1) lstm_persist(
        const float* __restrict__ bias,
        const float* __restrict__ gg, const float* __restrict__ gb,
        const float* __restrict__ cgam, const float* __restrict__ cbet,
        float* __restrict__ out) {
    extern __shared__ unsigned char sm8[];
    __half* Whs = (__half*)sm8;                      // [32][WST] Wh tile
    __half* Wxs = Whs + 32 * WST;                    // [32][WST] Wx tile
    __half* Ahs = Wxs + 32 * WST;                    // [64][WST] h tile
    __half* Xb  = Ahs + 64 * WST;                    // 2 x (Xh | Xl), 64 x WST each
    float* red = (float*)(Xb + 4 * 64 * WST);        // [32]

    const int blk = blockIdx.x;
    const int tid = threadIdx.x;
    const int lane = tid & 31;
    const int wid = tid >> 5;
    const int wm = wid & 3, wn = wid >> 2;           // 4m x 4n
    const int lr = lane >> 2, lc = lane & 3;

    const int jn = blk & 63;
    const int kc = blk >> 6;                          // 0 or 1
    const int jb = jn * 32;                           // N-col base
    const int k0 = kc * 256;                          // K base (both x and h halves)
    const bool writer = (blk < WRT);

    // one-time: resident W tiles [32 n][256 k] fp16 (Wh = cols DD+k0.., Wx = cols k0..)
    {
        int r = tid >> 4;                 // 0..31
        int seg = (tid & 15) * 16;
        const uint4* s = (const uint4*)&g_w16[(size_t)(jb + r) * KK + DD + k0 + seg];
        uint4* d = (uint4*)&Whs[r * WST + seg];
        d[0] = s[0]; d[1] = s[1];
        s = (const uint4*)&g_w16[(size_t)(jb + r) * KK + k0 + seg];
        d = (uint4*)&Wxs[r * WST + seg];
        d[0] = s[0]; d[1] = s[1];
    }

    // ldmatrix lane addressing (verified)
    const int a_g = lane >> 3;
    const int a_row_off = (a_g & 1) * 8 + (lane & 7);
    const int a_col_off = (a_g >> 1) * 8;
    const int b_row_off = lane & 7;
    const int b_col_off = ((lane >> 3) & 1) * 8;

    // phase-1 output coordinates
    const int p1_r = wm * 16 + lr;
    const int p1_c = jb + wn * 8 + lc * 2;

    // bias folded at partial store by kc==0 blocks (bias depends on column only)
    const float bias0 = (kc == 0) ? bias[p1_c] : 0.f;
    const float bias1 = (kc == 0) ? bias[p1_c + 1] : 0.f;

    // phase-2 constants (writers only; b = blk)
    const int b = blk;
    float gf = 0.f, bf = 0.f, gi = 0.f, bi = 0.f, gq = 0.f, bq = 0.f,
          go = 0.f, bo = 0.f, cga = 0.f, cbe = 0.f, creg = 0.f;
    if (writer) {
        gf = gg[tid];            bf = gb[tid];
        gi = gg[HH + tid];       bi = gb[HH + tid];
        gq = gg[2 * HH + tid];   bq = gb[2 * HH + tid];
        go = gg[3 * HH + tid];   bo = gb[3 * HH + tid];
        cga = cgam[tid];         cbe = cbet[tid];
        creg = g_c0[b * HH + tid];
    }
    float hlast = 0.f;

    // x prefetch addressing: 8 threads/row x 32 halfwords (4 cp16 per array)
    const int x_r = tid >> 3;                 // 0..63 (batch row)
    const int x_seg = (tid & 7) * 32;

    // fragment base pointers
    const __half* Abase  = &Ahs[(wm * 16 + a_row_off) * WST + a_col_off];
    const __half* Bh_base = &Whs[(wn * 8 + b_row_off) * WST + b_col_off];
    const __half* Bx_base = &Wxs[(wn * 8 + b_row_off) * WST + b_col_off];

    // prefetch x(0) and x(1)
    {
        // x(0) -> buf 0
        const __half* sh = &g_xhi[((size_t)0 * BB + x_r) * DD + k0 + x_seg];
        const __half* sl = &g_xlo[((size_t)0 * BB + x_r) * DD + k0 + x_seg];
        __half* dh = Xb + 0 * (2 * 64 * WST) + x_r * WST + x_seg;
        __half* dl = dh + 64 * WST;
        cp16(dh, sh); cp16(dh + 8, sh + 8); cp16(dh + 16, sh + 16); cp16(dh + 24, sh + 24);
        cp16(dl, sl); cp16(dl + 8, sl + 8); cp16(dl + 16, sl + 16); cp16(dl + 24, sl + 24);
        cp_commit();
        // x(1) -> buf 1
        sh = &g_xhi[((size_t)1 * BB + x_r) * DD + k0 + x_seg];
        sl = &g_xlo[((size_t)1 * BB + x_r) * DD + k0 + x_seg];
        dh = Xb + 1 * (2 * 64 * WST) + x_r * WST + x_seg;
        dl = dh + 64 * WST;
        cp16(dh, sh); cp16(dh + 8, sh + 8); cp16(dh + 16, sh + 16); cp16(dh + 24, sh + 24);
        cp16(dl, sl); cp16(dl + 8, sl + 8); cp16(dl + 16, sl + 16); cp16(dl + 24, sl + 24);
        cp_commit();
    }

    // x-MMA for step 0 (wait x(0) only; also covers W one-time smem stores)
    float accx[4] = {0.f, 0.f, 0.f, 0.f};
    asm volatile("cp.async.wait_group 1;");
    __syncthreads();
    {
        const __half* Xh = Xb + x_r * 0 /*dummy*/;   // silence unused warnings pattern
        const __half* Xhb = Xb + (wm * 16 + a_row_off) * WST + a_col_off;
        const __half* Xlb = Xhb + 64 * WST;
        (void)Xh;
#pragma unroll 8
        for (int ks = 0; ks < 256; ks += 16) {
            unsigned ah[4], al[4], bh[2];
            ldsm_x4(ah, Xhb + ks);
            ldsm_x4(al, Xlb + ks);
            ldsm_x2(bh, Bx_base + ks);
            mma_f16(accx, ah, bh);
            mma_f16(accx, al, bh);
        }
    }

    for (int t = 0; t < TT; t++) {
        // ----- phase 1: load h tile (64 x 256 fp16), h-MMA on top of accx -----
        {
            const uint4* s = (const uint4*)&g_h16[x_r * HH + k0 + x_seg];
            uint4* d = (uint4*)&Ahs[x_r * WST + x_seg];
            d[0] = __ldcg(s + 0); d[1] = __ldcg(s + 1);
            d[2] = __ldcg(s + 2); d[3] = __ldcg(s + 3);
        }
        __syncthreads();

        float acc[4] = {accx[0], accx[1], accx[2], accx[3]};

#pragma unroll 8
        for (int ks = 0; ks < 256; ks += 16) {
            unsigned ah[4], bh[2];
            ldsm_x4(ah, Abase + ks);
            ldsm_x2(bh, Bh_base + ks);
            mma_f16(acc, ah, bh);            // h x Wh
        }

        // store partial (+ bias on kc==0)
        {
            float2 v;
            v.x = acc[0] + bias0; v.y = acc[1] + bias1;
            *(float2*)&g_part[((size_t)kc * BB + p1_r) * GG + p1_c] = v;
            v.x = acc[2] + bias0; v.y = acc[3] + bias1;
            *(float2*)&g_part[((size_t)kc * BB + p1_r + 8) * GG + p1_c] = v;
        }

        unsigned valA = 2u * t + 1u;
        unsigned valB = 2u * t + 2u;
        bar_arrive(blk, valA);

        if (writer) {
            bar_wait_all(valA);

            // ----- phase 2: batch row b, one gate element per thread -----
            const float* p0 = g_part + (size_t)b * GG;
            const float* p1 = g_part + (size_t)(BB + b) * GG;
            float vf = __ldcg(&p0[tid])          + __ldcg(&p1[tid]);
            float vi = __ldcg(&p0[HH + tid])     + __ldcg(&p1[HH + tid]);
            float vq = __ldcg(&p0[2 * HH + tid]) + __ldcg(&p1[2 * HH + tid]);
            float vo = __ldcg(&p0[3 * HH + tid]) + __ldcg(&p1[3 * HH + tid]);

            float s = vf + vi + vq + vo;
            float sq = vf * vf + vi * vi + vq * vq + vo * vo;
            block_reduce2(s, sq, red);
            float mean = s * (1.f / GG);
            float var = sq * (1.f / GG) - mean * mean;
            float rstd = rsqrtf(var + EPSV);

            float f = fast_sig((vf - mean) * rstd * gf + bf);
            float i = fast_sig((vi - mean) * rstd * gi + bi);
            float q = fast_tanh((vq - mean) * rstd * gq + bq);
            float o = fast_sig((vo - mean) * rstd * go + bo);
            float c = f * creg + i * q;

            float s2 = c, sq2 = c * c;
            block_reduce2(s2, sq2, red);
            float mean2 = s2 * (1.f / HH);
            float var2 = sq2 * (1.f / HH) - mean2 * mean2;
            float rstd2 = rsqrtf(var2 + EPSV);

            float cn = (c - mean2) * rstd2 * cga + cbe;
            float hn = o * fast_tanh(cn);
            creg = cn;
            hlast = hn;

            g_h16[b * HH + tid] = __float2half(hn);

            bar_arrive(blk, valB);     // releases h store (st.release orders)

            out[((size_t)t * BB + b) * HH + tid] = hn;
        }

        // ----- x work for step t+1 (overlaps phase 2 / barrier-B window) -----
        accx[0] = accx[1] = accx[2] = accx[3] = 0.f;
        if (t + 1 < TT) {
            asm volatile("cp.async.wait_group 0;");   // x(t+1) landed
            __syncthreads();
            int par = (t + 1) & 1;
            const __half* Xhb = Xb + par * (2 * 64 * WST)
                              + (wm * 16 + a_row_off) * WST + a_col_off;
            const __half* Xlb = Xhb + 64 * WST;
#pragma unroll 8
            for (int ks = 0; ks < 256; ks += 16) {
                unsigned ah[4], al[4], bh[2];
                ldsm_x4(ah, Xhb + ks);
                ldsm_x4(al, Xlb + ks);
                ldsm_x2(bh, Bx_base + ks);
                mma_f16(accx, ah, bh);
                mma_f16(accx, al, bh);
            }
            if (t + 2 < TT) {
                // prefetch x(t+2) into buffer (t)&1 (consumed two iters ago)
                const __half* sh = &g_xhi[((size_t)(t + 2) * BB + x_r) * DD + k0 + x_seg];
                const __half* sl = &g_xlo[((size_t)(t + 2) * BB + x_r) * DD + k0 + x_seg];
                __half* dh = Xb + (t & 1) * (2 * 64 * WST) + x_r * WST + x_seg;
                __half* dl = dh + 64 * WST;
                cp16(dh, sh); cp16(dh + 8, sh + 8);
                cp16(dh + 16, sh + 16); cp16(dh + 24, sh + 24);
                cp16(dl, sl); cp16(dl + 8, sl + 8);
                cp16(dl + 16, sl + 16); cp16(dl + 24, sl + 24);
                cp_commit();
            }
        }

        bar_wait_writers(valB);
    }

    if (writer) {
        out[OUT_HC_OFF + b * HH + tid] = hlast;
        out[OUT_HC_OFF + BB * HH + b * HH + tid] = creg;
    }
}

// ---------------------------------------------------------------------------
extern "C" void kernel_launch(void* const* d_in, const int* in_sizes, int n_in,
                              void* d_out, int out_size) {
    const float* x    = (const float*)d_in[0];
    const float* h0   = (const float*)d_in[1];
    const float* c0   = (const float*)d_in[2];
    const float* w    = (const float*)d_in[3];
    const float* bias = (const float*)d_in[4];
    const float* gg   = (const float*)d_in[5];
    const float* gb   = (const float*)d_in[6];
    const float* cg   = (const float*)d_in[7];
    const float* cb   = (const float*)d_in[8];
    float* out = (float*)d_out;

    // smem: (32 Wh + 32 Wx + 64 h + 256 x) rows * WST hw * 2B + red
    const int persist_smem = (32 + 32 + 64 + 256) * WST * 2 + 128;  // 202880 B

    static bool attr_set = false;
    if (!attr_set) {
        cudaFuncSetAttribute(lstm_persist,
                             cudaFuncAttributeMaxDynamicSharedMemorySize, persist_smem);
        attr_set = true;
    }

    init_kernel<<<128, 256>>>(h0, c0);
    split_w_kernel<<<(KK * GG + 255) / 256, 256>>>(w);
    split_x_kernel<<<(int)(((size_t)MM * DD + 255) / 256), 256>>>(x);

    // fully fused: x-GEMM + recurrence + LN, all 1024 steps in one launch
    lstm_persist<<<NBLK, THR, persist_smem>>>(bias, gg, gb, cg, cb, out);
}

// round 17
// speedup vs baseline: 1.1837x; 1.1837x over previous
#include <cuda_runtime.h>
#include <cuda_fp16.h>
#include <math.h>

// Problem constants
#define TT 1024
#define BB 64
#define DD 512
#define HH 512
#define KK 1024            // D + H
#define GG 2048            // 4*H
#define EPSV 1e-5f
#define MM (TT * BB)       // 65536
#define OUT_HC_OFF (TT * BB * HH)
#define NBLK 128           // persistent blocks (<= 148 SMs)
#define WRT 64             // writer blocks (phase 2)
#define THR 512
#define WST 264            // persist smem halfword stride (conflict-free)
#define GXR 40             // gemm_x smem row stride (halfwords)
#define GX_ARR (128 * GXR)             // one array (hw)
#define GX_STG (3 * GX_ARR)            // one stage: Ah, Al, Bh

// Scratch (device globals — no runtime allocation allowed)
__device__ float g_xw[(size_t)MM * GG];                  // 512 MB
__device__ __half g_xhi[(size_t)MM * DD];
__device__ __half g_xlo[(size_t)MM * DD];
__device__ __half g_w16[(size_t)GG * KK];                // W^T [n][k], fp16
__device__ __half g_hhi[BB * HH];
__device__ __half g_hlo[BB * HH];
__device__ float g_c0[BB * HH];
__device__ float g_part[2 * BB * GG];                     // 2 K-halves of gates
__device__ unsigned g_flags[NBLK * 8];                    // barrier flags, 32B apart

__device__ __forceinline__ void split2h(float v, __half& hi, __half& lo) {
    hi = __float2half(v);
    lo = __float2half(v - __half2float(hi));
}

// fp16 HMMA m16n8k16 -> f32
__device__ __forceinline__ void mma_f16(float* d, const unsigned* a, const unsigned* b) {
    asm volatile(
        "mma.sync.aligned.m16n8k16.row.col.f32.f16.f16.f32 "
        "{%0,%1,%2,%3}, {%4,%5,%6,%7}, {%8,%9}, {%0,%1,%2,%3};\n"
        : "+f"(d[0]), "+f"(d[1]), "+f"(d[2]), "+f"(d[3])
        : "r"(a[0]), "r"(a[1]), "r"(a[2]), "r"(a[3]), "r"(b[0]), "r"(b[1]));
}

__device__ __forceinline__ void ldsm_x4(unsigned* r, const void* p) {
    unsigned addr = (unsigned)__cvta_generic_to_shared(p);
    asm volatile("ldmatrix.sync.aligned.m8n8.x4.shared.b16 {%0,%1,%2,%3}, [%4];"
        : "=r"(r[0]), "=r"(r[1]), "=r"(r[2]), "=r"(r[3]) : "r"(addr));
}
__device__ __forceinline__ void ldsm_x2(unsigned* r, const void* p) {
    unsigned addr = (unsigned)__cvta_generic_to_shared(p);
    asm volatile("ldmatrix.sync.aligned.m8n8.x2.shared.b16 {%0,%1}, [%2];"
        : "=r"(r[0]), "=r"(r[1]) : "r"(addr));
}

__device__ __forceinline__ void cp16(void* smem_dst, const void* gsrc) {
    unsigned d = (unsigned)__cvta_generic_to_shared(smem_dst);
    asm volatile("cp.async.cg.shared.global [%0], [%1], 16;" :: "r"(d), "l"(gsrc));
}
__device__ __forceinline__ void cp_commit() {
    asm volatile("cp.async.commit_group;");
}

__device__ __forceinline__ void st_release(unsigned* p, unsigned v) {
    asm volatile("st.release.gpu.u32 [%0], %1;" :: "l"(p), "r"(v) : "memory");
}
__device__ __forceinline__ unsigned ld_acquire(unsigned* p) {
    unsigned v;
    asm volatile("ld.acquire.gpu.u32 %0, [%1];" : "=r"(v) : "l"(p) : "memory");
    return v;
}

// flag barrier pieces (R7-verified protocol)
__device__ __forceinline__ void bar_arrive(int blk, unsigned val) {
    __syncthreads();
    if (threadIdx.x == 0) st_release(&g_flags[blk * 8], val);
}
__device__ __forceinline__ void bar_wait_all(unsigned val) {
    if (threadIdx.x < NBLK) {
        while (ld_acquire(&g_flags[threadIdx.x * 8]) < val) { }
    }
    __syncthreads();
}
__device__ __forceinline__ void bar_wait_writers(unsigned val) {
    if (threadIdx.x < WRT) {
        while (ld_acquire(&g_flags[threadIdx.x * 8]) < val) { }
    }
    __syncthreads();
}

__device__ __forceinline__ float fast_sig(float x) {
    return __fdividef(1.f, 1.f + __expf(-x));
}
__device__ __forceinline__ float fast_tanh(float x) {
    return __fdividef(2.f, 1.f + __expf(-2.f * x)) - 1.f;
}

// ---------------------------------------------------------------------------
__global__ void init_kernel(const float* __restrict__ h0,
                            const float* __restrict__ c0) {
    int i = blockIdx.x * blockDim.x + threadIdx.x;
    if (i < NBLK * 8) g_flags[i] = 0;
    if (i < BB * HH) {
        split2h(h0[i], g_hhi[i], g_hlo[i]);
        g_c0[i] = c0[i];
    }
}

__global__ void split_w_kernel(const float* __restrict__ w) {
    int idx = blockIdx.x * blockDim.x + threadIdx.x;
    if (idx < KK * GG) {
        int k = idx / GG;
        int n = idx % GG;
        g_w16[(size_t)n * KK + k] = __float2half(w[idx]);
    }
}

__global__ void split_x_kernel(const float* __restrict__ x) {
    size_t idx = (size_t)blockIdx.x * blockDim.x + threadIdx.x;
    if (idx < (size_t)MM * DD) {
        __half hi, lo;
        split2h(x[idx], hi, lo);
        g_xhi[idx] = hi;
        g_xlo[idx] = lo;
    }
}

// ---------------------------------------------------------------------------
// XW = X @ Wx + bias via fp16 split-A HMMA.  M=65536, N=2048, K=512.
// cp.async double-buffered staging (BK=32), 8 warps = 4m x 2n (warp 32x64).
// 2 CTAs/SM (smem 60KB x2, regs <=128): doubles latency-hiding warps.
// ---------------------------------------------------------------------------
__global__ void __launch_bounds__(256, 2) gemm_x_kernel(const float* __restrict__ bias) {
    extern __shared__ __half gx[];   // 2 stages x (Ah | Al | Bh), each 128 x GXR

    const int bn = blockIdx.x * 128;
    const int bm = blockIdx.y * 128;
    const int tid = threadIdx.x;
    const int wid = tid >> 5, lane = tid & 31;
    const int wm = wid & 3, wn = wid >> 2;      // 4m x 2n
    const int lr = lane >> 2, lc = lane & 3;

    // ldmatrix lane addressing (verified)
    const int a_g = lane >> 3;
    const int a_row_off = (a_g & 1) * 8 + (lane & 7);
    const int a_col_off = (a_g >> 1) * 8;
    const int b4_row = (lane & 7) + ((lane >> 4) & 1) * 8;
    const int b4_col = ((lane >> 3) & 1) * 8;

    float acc[2][8][4];
#pragma unroll
    for (int i = 0; i < 2; i++)
#pragma unroll
        for (int j = 0; j < 8; j++)
#pragma unroll
            for (int q = 0; q < 4; q++) acc[i][j][q] = 0.f;

    // staging: 2 threads/row, each owns 16 halfwords (2 cp16) per array
    const int sr = tid >> 1;                 // 0..127
    const int sh = (tid & 1) * 16;           // halfword offset within 32
    const __half* srcAh = &g_xhi[(size_t)(bm + sr) * DD + sh];
    const __half* srcAl = &g_xlo[(size_t)(bm + sr) * DD + sh];
    const __half* srcB  = &g_w16[(size_t)(bn + sr) * KK + sh];
    __half* dst0 = gx + sr * GXR + sh;

#define STAGE_LOAD(s, k0)                                                     \
    do {                                                                      \
        __half* d = dst0 + (s) * GX_STG;                                      \
        cp16(d, srcAh + (k0));            cp16(d + 8, srcAh + (k0) + 8);      \
        d += GX_ARR;                                                          \
        cp16(d, srcAl + (k0));            cp16(d + 8, srcAl + (k0) + 8);      \
        d += GX_ARR;                                                          \
        cp16(d, srcB + (k0));             cp16(d + 8, srcB + (k0) + 8);       \
        cp_commit();                                                          \
    } while (0)

    STAGE_LOAD(0, 0);

    for (int kt = 0; kt < 16; kt++) {
        if (kt + 1 < 16) {
            STAGE_LOAD((kt + 1) & 1, (kt + 1) * 32);
            asm volatile("cp.async.wait_group 1;");
        } else {
            asm volatile("cp.async.wait_group 0;");
        }
        __syncthreads();

        const __half* Ah = gx + (kt & 1) * GX_STG;
        const __half* Al = Ah + GX_ARR;
        const __half* Bh = Al + GX_ARR;

#pragma unroll
        for (int ks = 0; ks < 32; ks += 16) {
            unsigned ahi[2][4], alo[2][4], bh[4][4];
#pragma unroll
            for (int im = 0; im < 2; im++) {
                ldsm_x4(ahi[im], &Ah[(wm * 32 + im * 16 + a_row_off) * GXR + ks + a_col_off]);
                ldsm_x4(alo[im], &Al[(wm * 32 + im * 16 + a_row_off) * GXR + ks + a_col_off]);
            }
#pragma unroll
            for (int inp = 0; inp < 4; inp++) {
                ldsm_x4(bh[inp], &Bh[(wn * 64 + inp * 16 + b4_row) * GXR + ks + b4_col]);
            }
#pragma unroll
            for (int im = 0; im < 2; im++)
#pragma unroll
                for (int in = 0; in < 8; in++) {
                    const unsigned* bf = bh[in >> 1] + (in & 1) * 2;
                    mma_f16(acc[im][in], ahi[im], bf);
                    mma_f16(acc[im][in], alo[im], bf);
                }
        }
        __syncthreads();   // stage consumed before it is overwritten
    }

#pragma unroll
    for (int im = 0; im < 2; im++)
#pragma unroll
        for (int in = 0; in < 8; in++) {
            int row = bm + wm * 32 + im * 16 + lr;
            int col = bn + wn * 64 + in * 8 + lc * 2;
            float b0 = bias[col], b1 = bias[col + 1];
            float2 v;
            v.x = acc[im][in][0] + b0; v.y = acc[im][in][1] + b1;
            *(float2*)&g_xw[(size_t)row * GG + col] = v;
            v.x = acc[im][in][2] + b0; v.y = acc[im][in][3] + b1;
            *(float2*)&g_xw[(size_t)(row + 8) * GG + col] = v;
        }
#undef STAGE_LOAD
}

// ---------------------------------------------------------------------------
// fast two-level block reduction (512 threads = 16 warps) — verified
// ---------------------------------------------------------------------------
__device__ __forceinline__ void block_reduce2(float& s, float& sq, float* shm) {
    int lane = threadIdx.x & 31;
    int wrp = threadIdx.x >> 5;
#pragma unroll
    for (int o = 16; o > 0; o >>= 1) {
        s  += __shfl_xor_sync(0xffffffffu, s, o);
        sq += __shfl_xor_sync(0xffffffffu, sq, o);
    }
    if (lane == 0) { shm[wrp] = s; shm[16 + wrp] = sq; }
    __syncthreads();
    if (wrp == 0) {
        float a = (lane < 16) ? shm[lane] : 0.f;
        float b = (lane < 16) ? shm[16 + lane] : 0.f;
#pragma unroll
        for (int o = 8; o > 0; o >>= 1) {
            a += __shfl_xor_sync(0xffffffffu, a, o);
            b += __shfl_xor_sync(0xffffffffu, b, o);
        }
        if (lane == 0) { shm[0] = a; shm[16] = b; }
    }
    __syncthreads();
    s = shm[0];
    sq = shm[16];
}

// ---------------------------------------------------------------------------
// Persistent recurrence: 128 blocks x 512 threads (16 warps = 4m x 4n).
// R12/R15-verified version, byte-identical (best measured).
// ---------------------------------------------------------------------------
__global__ void __launch_bounds__(THR, 1) lstm_persist(
        const float* __restrict__ gg, const float* __restrict__ gb,
        const float* __restrict__ cgam, const float* __restrict__ cbet,
        float* __restrict__ out) {
    extern __shared__ unsigned char sm8[];
    __half* Whs = (__half*)sm8;                      // [32][WST] fp16 W
    __half* Ahs = Whs + 32 * WST;                    // [64][WST]
    __half* Als = Ahs + 64 * WST;                    // [64][WST]
    float* red = (float*)(Als + 64 * WST);           // [32]

    const int blk = blockIdx.x;
    const int tid = threadIdx.x;
    const int lane = tid & 31;
    const int wid = tid >> 5;
    const int wm = wid & 3, wn = wid >> 2;           // 4m x 4n
    const int lr = lane >> 2, lc = lane & 3;

    const int jn = blk & 63;
    const int kc = blk >> 6;                          // 0 or 1
    const int jb = jn * 32;                           // N-col base
    const int k0 = kc * 256;                          // K base within Wh
    const bool writer = (blk < WRT);

    // one-time: resident W tile [32 n][256 k] fp16
    {
        int r = tid >> 4;                 // 0..31
        int seg = (tid & 15) * 16;
        const uint4* s = (const uint4*)&g_w16[(size_t)(jb + r) * KK + DD + k0 + seg];
        uint4* d = (uint4*)&Whs[r * WST + seg];
        d[0] = s[0]; d[1] = s[1];
    }

    // ldmatrix lane addressing (verified)
    const int a_g = lane >> 3;
    const int a_row_off = (a_g & 1) * 8 + (lane & 7);
    const int a_col_off = (a_g >> 1) * 8;
    const int b_row_off = lane & 7;
    const int b_col_off = ((lane >> 3) & 1) * 8;

    // phase-1 output coordinates
    const int p1_r = wm * 16 + lr;
    const int p1_c = jb + wn * 8 + lc * 2;

    // phase-2 constants (writers only; b = blk)
    const int b = blk;
    float gf = 0.f, bf = 0.f, gi = 0.f, bi = 0.f, gq = 0.f, bq = 0.f,
          go = 0.f, bo = 0.f, cga = 0.f, cbe = 0.f, creg = 0.f;
    if (writer) {
        gf = gg[tid];            bf = gb[tid];
        gi = gg[HH + tid];       bi = gb[HH + tid];
        gq = gg[2 * HH + tid];   bq = gb[2 * HH + tid];
        go = gg[3 * HH + tid];   bo = gb[3 * HH + tid];
        cga = cgam[tid];         cbe = cbet[tid];
        creg = g_c0[b * HH + tid];
    }
    float hlast = 0.f;

    // xw prefetch (kc==0 blocks fold xw into their partial)
    float2 xwA = make_float2(0.f, 0.f), xwB = xwA;
    if (kc == 0) {
        xwA = __ldcg((const float2*)&g_xw[(size_t)p1_r * GG + p1_c]);
        xwB = __ldcg((const float2*)&g_xw[(size_t)(p1_r + 8) * GG + p1_c]);
    }

    const __half* Abase_h = &Ahs[(wm * 16 + a_row_off) * WST + a_col_off];
    const __half* Abase_l = &Als[(wm * 16 + a_row_off) * WST + a_col_off];
    const __half* Bbase2 = &Whs[(wn * 8 + b_row_off) * WST + b_col_off];

    for (int t = 0; t < TT; t++) {
        // ----- phase 1: load h tile (64 x 256 hi/lo) -----
        {
            int r = tid >> 3;                 // 0..63
            int seg = (tid & 7) * 32;
            const uint4* s = (const uint4*)&g_hhi[r * HH + k0 + seg];
            uint4* d = (uint4*)&Ahs[r * WST + seg];
            d[0] = __ldcg(s + 0); d[1] = __ldcg(s + 1);
            d[2] = __ldcg(s + 2); d[3] = __ldcg(s + 3);
            s = (const uint4*)&g_hlo[r * HH + k0 + seg];
            d = (uint4*)&Als[r * WST + seg];
            d[0] = __ldcg(s + 0); d[1] = __ldcg(s + 1);
            d[2] = __ldcg(s + 2); d[3] = __ldcg(s + 3);
        }
        __syncthreads();

        float acc[4] = {0.f, 0.f, 0.f, 0.f};

#pragma unroll 8
        for (int ks = 0; ks < 256; ks += 16) {
            unsigned ah[4], al[4], bh[2];
            ldsm_x4(ah, Abase_h + ks);
            ldsm_x4(al, Abase_l + ks);
            ldsm_x2(bh, Bbase2 + ks);
            mma_f16(acc, ah, bh);            // h_hi x W
            mma_f16(acc, al, bh);            // h_lo x W
        }

        // store partial (+ xw for kc==0)
        {
            float2 v;
            v.x = acc[0] + xwA.x; v.y = acc[1] + xwA.y;
            *(float2*)&g_part[((size_t)kc * BB + p1_r) * GG + p1_c] = v;
            v.x = acc[2] + xwB.x; v.y = acc[3] + xwB.y;
            *(float2*)&g_part[((size_t)kc * BB + p1_r + 8) * GG + p1_c] = v;
        }

        unsigned valA = 2u * t + 1u;
        unsigned valB = 2u * t + 2u;
        bar_arrive(blk, valA);

        if (writer) {
            bar_wait_all(valA);

            // ----- phase 2: batch row b, one gate element per thread -----
            const float* p0 = g_part + (size_t)b * GG;
            const float* p1 = g_part + (size_t)(BB + b) * GG;
            float vf = __ldcg(&p0[tid])          + __ldcg(&p1[tid]);
            float vi = __ldcg(&p0[HH + tid])     + __ldcg(&p1[HH + tid]);
            float vq = __ldcg(&p0[2 * HH + tid]) + __ldcg(&p1[2 * HH + tid]);
            float vo = __ldcg(&p0[3 * HH + tid]) + __ldcg(&p1[3 * HH + tid]);

            float s = vf + vi + vq + vo;
            float sq = vf * vf + vi * vi + vq * vq + vo * vo;
            block_reduce2(s, sq, red);
            float mean = s * (1.f / GG);
            float var = sq * (1.f / GG) - mean * mean;
            float rstd = rsqrtf(var + EPSV);

            float f = fast_sig((vf - mean) * rstd * gf + bf);
            float i = fast_sig((vi - mean) * rstd * gi + bi);
            float q = fast_tanh((vq - mean) * rstd * gq + bq);
            float o = fast_sig((vo - mean) * rstd * go + bo);
            float c = f * creg + i * q;

            float s2 = c, sq2 = c * c;
            block_reduce2(s2, sq2, red);
            float mean2 = s2 * (1.f / HH);
            float var2 = sq2 * (1.f / HH) - mean2 * mean2;
            float rstd2 = rsqrtf(var2 + EPSV);

            float cn = (c - mean2) * rstd2 * cga + cbe;
            float hn = o * fast_tanh(cn);
            creg = cn;
            hlast = hn;

            __half hi, lo;
            split2h(hn, hi, lo);
            g_hhi[b * HH + tid] = hi;
            g_hlo[b * HH + tid] = lo;

            bar_arrive(blk, valB);     // releases h stores (st.release orders)

            out[((size_t)t * BB + b) * HH + tid] = hn;
        }

        // prefetch next step's xw while waiting (kc==0 only)
        if (kc == 0 && t + 1 < TT) {
            size_t tb = (size_t)(t + 1) * BB;
            xwA = __ldcg((const float2*)&g_xw[(tb + p1_r) * GG + p1_c]);
            xwB = __ldcg((const float2*)&g_xw[(tb + p1_r + 8) * GG + p1_c]);
        }

        bar_wait_writers(valB);
    }

    if (writer) {
        out[OUT_HC_OFF + b * HH + tid] = hlast;
        out[OUT_HC_OFF + BB * HH + b * HH + tid] = creg;
    }
}

// ---------------------------------------------------------------------------
extern "C" void kernel_launch(void* const* d_in, const int* in_sizes, int n_in,
                              void* d_out, int out_size) {
    const float* x    = (const float*)d_in[0];
    const float* h0   = (const float*)d_in[1];
    const float* c0   = (const float*)d_in[2];
    const float* w    = (const float*)d_in[3];
    const float* bias = (const float*)d_in[4];
    const float* gg   = (const float*)d_in[5];
    const float* gb   = (const float*)d_in[6];
    const float* cg   = (const float*)d_in[7];
    const float* cb   = (const float*)d_in[8];
    float* out = (float*)d_out;

    const int persist_smem = 160 * WST * 2 + 256;
    const int gemm_smem = 2 * GX_STG * 2;      // 61440 B

    static bool attr_set = false;
    if (!attr_set) {
        cudaFuncSetAttribute(lstm_persist,
                             cudaFuncAttributeMaxDynamicSharedMemorySize, persist_smem);
        cudaFuncSetAttribute(gemm_x_kernel,
                             cudaFuncAttributeMaxDynamicSharedMemorySize, gemm_smem);
        attr_set = true;
    }

    init_kernel<<<128, 256>>>(h0, c0);
    split_w_kernel<<<(KK * GG + 255) / 256, 256>>>(w);
    split_x_kernel<<<(int)(((size_t)MM * DD + 255) / 256), 256>>>(x);

    // XW = X @ Wx + bias : M=65536, N=2048, K=512
    gemm_x_kernel<<<dim3(GG / 128, MM / 128), 256, gemm_smem>>>(bias);

    // persistent recurrence: all 1024 steps in one launch
    lstm_persist<<<NBLK, THR, persist_smem>>>(gg, gb, cg, cb, out);
}